// round 1
// baseline (speedup 1.0000x reference)
#include <cuda_runtime.h>
#include <math.h>

#define TOK   50176      // B*H*W tokens
#define CDIM  512
#define HID   2048
#define NHEAD 16
#define NTOKW 49         // tokens per window
#define NWIN  1024       // B * 64

// ---------------- scratch (device globals; no allocation) ----------------
__device__ float g_qkv    [(size_t)TOK * 1536];
__device__ float g_attnout[(size_t)TOK * CDIM];
__device__ float g_proj   [(size_t)TOK * CDIM];
__device__ float g_x1     [(size_t)TOK * CDIM];
__device__ float g_hidden [(size_t)TOK * HID];
__device__ float g_h2     [(size_t)TOK * CDIM];
__device__ float g_table  [169 * 16];
__device__ float g_biasT  [16 * 2401];

// ---------------- index helpers ----------------
// window-ordered token t -> pixel row in x (applies roll(-3,-3) + window partition)
__device__ __forceinline__ int qkv_src_row(int t) {
    int b   = t / 3136;
    int r5  = t - b * 3136;
    int win = r5 / NTOKW;
    int n   = r5 - win * NTOKW;
    int wh = win >> 3, ww = win & 7;
    int rr = n / 7,    cc = n - (n / 7) * 7;
    int hs = wh * 7 + rr, ws = ww * 7 + cc;
    int h = hs + 3; if (h >= 56) h -= 56;
    int w = ws + 3; if (w >= 56) w -= 56;
    return (b * 56 + h) * 56 + w;
}

// ---------------- CPB MLP: table[169][16] ----------------
__global__ void cpb_table_kernel(const float* __restrict__ rct,
                                 const float* __restrict__ w1,
                                 const float* __restrict__ b1,
                                 const float* __restrict__ w2) {
    int pos = blockIdx.x;                 // 0..168
    float t0 = rct[pos * 2 + 0];
    float t1 = rct[pos * 2 + 1];
    __shared__ float hid[512];
    int j = threadIdx.x;                  // 512 threads
    float hv = t0 * w1[j] + t1 * w1[512 + j] + b1[j];
    hid[j] = fmaxf(hv, 0.f);
    __syncthreads();
    int warp = j >> 5, lane = j & 31;     // 16 warps -> 16 heads
    float s = 0.f;
    for (int jj = lane; jj < 512; jj += 32) s += hid[jj] * w2[jj * 16 + warp];
    #pragma unroll
    for (int o = 16; o > 0; o >>= 1) s += __shfl_down_sync(0xffffffffu, s, o);
    if (lane == 0) g_table[pos * 16 + warp] = s;
}

__global__ void bias_expand_kernel(const int* __restrict__ rpi) {
    int i = blockIdx.x * blockDim.x + threadIdx.x;  // 16*2401
    if (i >= 16 * 2401) return;
    int h = i / 2401, nm = i - h * 2401;
    float v = g_table[rpi[nm] * 16 + h];
    g_biasT[i] = 16.f / (1.f + expf(-v));
}

// ---------------- tiled fp32 GEMM: C[M,N] = A[M,K] @ B[K,N] + epilogue -----
#define BM 128
#define BN 128
#define BK 16
#define MODE_BIAS      0
#define MODE_QKV       1   // A gathered from x (roll+partition), bias = [q,0,v]
#define MODE_BIAS_GELU 2

template <int MODE>
__global__ __launch_bounds__(256)
void sgemm_kernel(const float* __restrict__ A, const float* __restrict__ B,
                  float* __restrict__ C, int M, int N, int K,
                  const float* __restrict__ bias, const float* __restrict__ bias2) {
    __shared__ float As[BK][BM];
    __shared__ float Bs[BK][BN];
    __shared__ int   srcOff[BM];

    int tid = threadIdx.x;
    int rowBase = blockIdx.y * BM;
    int colBase = blockIdx.x * BN;

    if (tid < BM) {
        int r = rowBase + tid;
        srcOff[tid] = (MODE == MODE_QKV) ? qkv_src_row(r) * 512 : r * K;
    }
    __syncthreads();

    float acc[8][8];
    #pragma unroll
    for (int i = 0; i < 8; i++)
        #pragma unroll
        for (int j = 0; j < 8; j++) acc[i][j] = 0.f;

    int tm = (tid >> 4) << 3;
    int tn = (tid & 15) << 3;

    int ar0 = tid >> 2,       ac0 = (tid & 3) << 2;   // A: 128 rows x 4 float4
    int ar1 = ar0 + 64;
    int br0 = tid >> 5,       bc0 = (tid & 31) << 2;  // B: 16 rows x 32 float4
    int br1 = br0 + 8;

    for (int kt = 0; kt < K; kt += BK) {
        float4 a0 = *(const float4*)(A + srcOff[ar0] + kt + ac0);
        float4 a1 = *(const float4*)(A + srcOff[ar1] + kt + ac0);
        float4 b0 = *(const float4*)(B + (size_t)(kt + br0) * N + colBase + bc0);
        float4 b1 = *(const float4*)(B + (size_t)(kt + br1) * N + colBase + bc0);
        __syncthreads();
        As[ac0 + 0][ar0] = a0.x; As[ac0 + 1][ar0] = a0.y;
        As[ac0 + 2][ar0] = a0.z; As[ac0 + 3][ar0] = a0.w;
        As[ac0 + 0][ar1] = a1.x; As[ac0 + 1][ar1] = a1.y;
        As[ac0 + 2][ar1] = a1.z; As[ac0 + 3][ar1] = a1.w;
        *(float4*)&Bs[br0][bc0] = b0;
        *(float4*)&Bs[br1][bc0] = b1;
        __syncthreads();

        #pragma unroll
        for (int k = 0; k < BK; k++) {
            float4 av0 = *(const float4*)&As[k][tm];
            float4 av1 = *(const float4*)&As[k][tm + 4];
            float4 bv0 = *(const float4*)&Bs[k][tn];
            float4 bv1 = *(const float4*)&Bs[k][tn + 4];
            float a[8] = {av0.x, av0.y, av0.z, av0.w, av1.x, av1.y, av1.z, av1.w};
            float b[8] = {bv0.x, bv0.y, bv0.z, bv0.w, bv1.x, bv1.y, bv1.z, bv1.w};
            #pragma unroll
            for (int i = 0; i < 8; i++)
                #pragma unroll
                for (int j = 0; j < 8; j++) acc[i][j] += a[i] * b[j];
        }
    }

    #pragma unroll
    for (int i = 0; i < 8; i++) {
        int row = rowBase + tm + i;
        size_t co = (size_t)row * N + colBase + tn;
        #pragma unroll
        for (int j = 0; j < 8; j++) {
            float v = acc[i][j];
            int col = colBase + tn + j;
            if (MODE == MODE_QKV) {
                v += (col < 512) ? bias[col] : ((col < 1024) ? 0.f : bias2[col - 1024]);
            } else {
                v += bias[col];
                if (MODE == MODE_BIAS_GELU)
                    v = 0.5f * v * (1.f + erff(v * 0.70710678118654752f));
            }
            C[co + j] = v;
        }
    }
}

// ---------------- per-(window, head) attention ----------------
__global__ __launch_bounds__(256)
void attn_kernel(const float* __restrict__ mask,
                 const float* __restrict__ logit_scale) {
    int blk  = blockIdx.x;
    int win  = blk >> 4;
    int head = blk & 15;
    const int T = 256;
    __shared__ float qs[NTOKW * 32], ks[NTOKW * 32], vs[NTOKW * 32];
    __shared__ float S[NTOKW * NTOKW];
    __shared__ float rqn[NTOKW], rkn[NTOKW];
    int tid = threadIdx.x;

    size_t base = (size_t)win * NTOKW * 1536 + head * 32;
    for (int i = tid; i < NTOKW * 32; i += T) {
        int n = i >> 5, d = i & 31;
        size_t o = base + (size_t)n * 1536 + d;
        qs[i] = g_qkv[o];
        ks[i] = g_qkv[o + 512];
        vs[i] = g_qkv[o + 1024];
    }
    __syncthreads();

    if (tid < 2 * NTOKW) {
        int n = tid % NTOKW;
        const float* p = (tid < NTOKW) ? (qs + n * 32) : (ks + n * 32);
        float s = 0.f;
        #pragma unroll
        for (int d = 0; d < 32; d++) { float v = p[d]; s += v * v; }
        float inv = rsqrtf(s);
        if (tid < NTOKW) rqn[n] = inv; else rkn[n] = inv;
    }
    float scale = expf(fminf(logit_scale[head], 4.6051701859880914f)); // ln(100)
    __syncthreads();

    const float* bh = g_biasT + head * 2401;
    const float* mw = mask + (size_t)(win & 63) * 2401;
    for (int p = tid; p < 2401; p += T) {
        int n = p / NTOKW, m = p - n * NTOKW;
        const float* qp = qs + n * 32;
        const float* kp = ks + m * 32;
        float s = 0.f;
        #pragma unroll
        for (int d = 0; d < 32; d++) s += qp[d] * kp[d];
        S[p] = s * rqn[n] * rkn[m] * scale + bh[p] + mw[p];
    }
    __syncthreads();

    if (tid < NTOKW) {
        float* row = S + tid * NTOKW;
        float mx = row[0];
        for (int m = 1; m < NTOKW; m++) mx = fmaxf(mx, row[m]);
        float sum = 0.f;
        for (int m = 0; m < NTOKW; m++) { float e = expf(row[m] - mx); row[m] = e; sum += e; }
        float inv = 1.f / sum;
        for (int m = 0; m < NTOKW; m++) row[m] *= inv;
    }
    __syncthreads();

    for (int i = tid; i < NTOKW * 32; i += T) {
        int n = i >> 5, d = i & 31;
        const float* Pr = S + n * NTOKW;
        float s = 0.f;
        #pragma unroll
        for (int m = 0; m < NTOKW; m++) s += Pr[m] * vs[m * 32 + d];
        g_attnout[(size_t)(win * NTOKW + n) * CDIM + head * 32 + d] = s;
    }
}

// ---------------- LayerNorm + residual helpers ----------------
__device__ __forceinline__ void block_reduce2(float& s, float& ss) {
    __shared__ float red[32];
    int lane = threadIdx.x & 31, warp = threadIdx.x >> 5;
    #pragma unroll
    for (int o = 16; o > 0; o >>= 1) {
        s  += __shfl_down_sync(0xffffffffu, s,  o);
        ss += __shfl_down_sync(0xffffffffu, ss, o);
    }
    if (lane == 0) { red[warp] = s; red[warp + 16] = ss; }
    __syncthreads();
    if (threadIdx.x == 0) {
        float a = 0.f, b = 0.f;
        int nw = blockDim.x >> 5;
        for (int w = 0; w < nw; w++) { a += red[w]; b += red[w + 16]; }
        red[0] = a; red[16] = b;
    }
    __syncthreads();
    s = red[0]; ss = red[16];
    __syncthreads();
}

// x1[pixel] = x[pixel] + LN(proj[window-token for that pixel])
__global__ __launch_bounds__(128)
void post_attn_kernel(const float* __restrict__ x,
                      const float* __restrict__ g1, const float* __restrict__ b1) {
    int p = blockIdx.x;
    int b = p / 3136, rem = p - b * 3136;
    int h = rem / 56, w = rem - (rem / 56) * 56;
    int hs = h - 3; if (hs < 0) hs += 56;
    int ws = w - 3; if (ws < 0) ws += 56;
    int t = (b * 64 + (hs / 7) * 8 + (ws / 7)) * NTOKW + (hs % 7) * 7 + (ws % 7);
    const float* row = g_proj + (size_t)t * CDIM;
    float s = 0.f, ss = 0.f;
    for (int c = threadIdx.x; c < CDIM; c += blockDim.x) {
        float v = row[c]; s += v; ss += v * v;
    }
    block_reduce2(s, ss);
    float mu = s * (1.f / CDIM);
    float var = ss * (1.f / CDIM) - mu * mu;
    float rstd = rsqrtf(var + 1e-5f);
    const float* xr = x + (size_t)p * CDIM;
    float* o = g_x1 + (size_t)p * CDIM;
    for (int c = threadIdx.x; c < CDIM; c += blockDim.x)
        o[c] = xr[c] + (row[c] - mu) * rstd * g1[c] + b1[c];
}

// out[pixel] = x1[pixel] + LN(h2[pixel])
__global__ __launch_bounds__(128)
void final_kernel(const float* __restrict__ g2, const float* __restrict__ b2,
                  float* __restrict__ out) {
    int p = blockIdx.x;
    const float* row = g_h2 + (size_t)p * CDIM;
    float s = 0.f, ss = 0.f;
    for (int c = threadIdx.x; c < CDIM; c += blockDim.x) {
        float v = row[c]; s += v; ss += v * v;
    }
    block_reduce2(s, ss);
    float mu = s * (1.f / CDIM);
    float var = ss * (1.f / CDIM) - mu * mu;
    float rstd = rsqrtf(var + 1e-5f);
    const float* xr = g_x1 + (size_t)p * CDIM;
    float* o = out + (size_t)p * CDIM;
    for (int c = threadIdx.x; c < CDIM; c += blockDim.x)
        o[c] = xr[c] + (row[c] - mu) * rstd * g2[c] + b2[c];
}

// ---------------- launch ----------------
extern "C" void kernel_launch(void* const* d_in, const int* in_sizes, int n_in,
                              void* d_out, int out_size) {
    const float* x        = (const float*)d_in[0];
    const float* qkv_w    = (const float*)d_in[1];
    const float* q_bias   = (const float*)d_in[2];
    const float* v_bias   = (const float*)d_in[3];
    const float* proj_w   = (const float*)d_in[4];
    const float* proj_b   = (const float*)d_in[5];
    const float* lscale   = (const float*)d_in[6];
    const float* cpb_w1   = (const float*)d_in[7];
    const float* cpb_b1   = (const float*)d_in[8];
    const float* cpb_w2   = (const float*)d_in[9];
    const float* rct      = (const float*)d_in[10];
    const float* gamma1   = (const float*)d_in[11];
    const float* beta1    = (const float*)d_in[12];
    const float* gamma2   = (const float*)d_in[13];
    const float* beta2    = (const float*)d_in[14];
    const float* fc1_w    = (const float*)d_in[15];
    const float* fc1_b    = (const float*)d_in[16];
    const float* fc2_w    = (const float*)d_in[17];
    const float* fc2_b    = (const float*)d_in[18];
    const int*   rpi      = (const int*)d_in[19];
    const float* amask    = (const float*)d_in[20];
    float* out = (float*)d_out;

    float *p_qkv, *p_attn, *p_proj, *p_x1, *p_hid, *p_h2;
    cudaGetSymbolAddress((void**)&p_qkv,  g_qkv);
    cudaGetSymbolAddress((void**)&p_attn, g_attnout);
    cudaGetSymbolAddress((void**)&p_proj, g_proj);
    cudaGetSymbolAddress((void**)&p_x1,   g_x1);
    cudaGetSymbolAddress((void**)&p_hid,  g_hidden);
    cudaGetSymbolAddress((void**)&p_h2,   g_h2);

    // 1. continuous position bias
    cpb_table_kernel<<<169, 512>>>(rct, cpb_w1, cpb_b1, cpb_w2);
    bias_expand_kernel<<<(16 * 2401 + 255) / 256, 256>>>(rpi);

    // 2. QKV GEMM (A gathered: roll + window partition fused)
    sgemm_kernel<MODE_QKV><<<dim3(1536 / BN, TOK / BM), 256>>>(
        x, qkv_w, p_qkv, TOK, 1536, 512, q_bias, v_bias);

    // 3. windowed cosine attention
    attn_kernel<<<NWIN * NHEAD, 256>>>(amask, lscale);

    // 4. output projection
    sgemm_kernel<MODE_BIAS><<<dim3(CDIM / BN, TOK / BM), 256>>>(
        p_attn, proj_w, p_proj, TOK, CDIM, CDIM, proj_b, nullptr);

    // 5. window reverse + un-roll + LN + residual  -> x1 (pixel order)
    post_attn_kernel<<<TOK, 128>>>(x, gamma1, beta1);

    // 6. MLP
    sgemm_kernel<MODE_BIAS_GELU><<<dim3(HID / BN, TOK / BM), 256>>>(
        p_x1, fc1_w, p_hid, TOK, HID, 512, fc1_b, nullptr);
    sgemm_kernel<MODE_BIAS><<<dim3(CDIM / BN, TOK / BM), 256>>>(
        p_hid, fc2_w, p_h2, TOK, CDIM, HID, fc2_b, nullptr);

    // 7. final LN + residual
    final_kernel<<<TOK, 128>>>(gamma2, beta2, out);
}

// round 2
// speedup vs baseline: 1.8020x; 1.8020x over previous
#include <cuda_runtime.h>
#include <math.h>

#define TOK   50176      // B*H*W tokens
#define CDIM  512
#define HID   2048
#define NHEAD 16
#define NTOKW 49         // tokens per window
#define NWIN  1024       // B * 64

// ---------------- scratch (device globals; no allocation) ----------------
__device__ float g_qkv    [(size_t)TOK * 1536];
__device__ float g_attnout[(size_t)TOK * CDIM];
__device__ float g_proj   [(size_t)TOK * CDIM];
__device__ float g_x1     [(size_t)TOK * CDIM];
__device__ float g_hidden [(size_t)TOK * HID];
__device__ float g_h2     [(size_t)TOK * CDIM];
__device__ float g_table  [169 * 16];
__device__ float g_biasT  [16 * 2401];

// ---------------- index helpers ----------------
// window-ordered token t -> pixel row in x (applies roll(-3,-3) + window partition)
__device__ __forceinline__ int qkv_src_row(int t) {
    int b   = t / 3136;
    int r5  = t - b * 3136;
    int win = r5 / NTOKW;
    int n   = r5 - win * NTOKW;
    int wh = win >> 3, ww = win & 7;
    int rr = n / 7,    cc = n - (n / 7) * 7;
    int hs = wh * 7 + rr, ws = ww * 7 + cc;
    int h = hs + 3; if (h >= 56) h -= 56;
    int w = ws + 3; if (w >= 56) w -= 56;
    return (b * 56 + h) * 56 + w;
}

// ---------------- CPB MLP: table[169][16] ----------------
__global__ void cpb_table_kernel(const float* __restrict__ rct,
                                 const float* __restrict__ w1,
                                 const float* __restrict__ b1,
                                 const float* __restrict__ w2) {
    int pos = blockIdx.x;                 // 0..168
    float t0 = rct[pos * 2 + 0];
    float t1 = rct[pos * 2 + 1];
    __shared__ float hid[512];
    int j = threadIdx.x;                  // 512 threads
    float hv = t0 * w1[j] + t1 * w1[512 + j] + b1[j];
    hid[j] = fmaxf(hv, 0.f);
    __syncthreads();
    int warp = j >> 5, lane = j & 31;     // 16 warps -> 16 heads
    float s = 0.f;
    for (int jj = lane; jj < 512; jj += 32) s += hid[jj] * w2[jj * 16 + warp];
    #pragma unroll
    for (int o = 16; o > 0; o >>= 1) s += __shfl_down_sync(0xffffffffu, s, o);
    if (lane == 0) g_table[pos * 16 + warp] = s;
}

__global__ void bias_expand_kernel(const int* __restrict__ rpi) {
    int i = blockIdx.x * blockDim.x + threadIdx.x;  // 16*2401
    if (i >= 16 * 2401) return;
    int h = i / 2401, nm = i - h * 2401;
    float v = g_table[rpi[nm] * 16 + h];
    g_biasT[i] = 16.f / (1.f + expf(-v));
}

// ---------------- tf32 tensor-core GEMM ----------------
// C[M,N] = A[M,K] @ B[K,N] + epilogue.  Block tile 256x128, 8 warps (4x2),
// warp tile 64x64, BK=16, double-buffered SMEM, mma.sync.m16n8k8 tf32.
#define MODE_BIAS      0
#define MODE_QKV       1   // A gathered from x (roll+partition), bias = [q,0,v]
#define MODE_BIAS_GELU 2

#define TBM 256
#define TBN 128
#define TBK 16
#define AS_STRIDE 20       // conflict-free: banks (20g+t)%32 distinct
#define BS_STRIDE 136      // conflict-free: banks (8t+g)%32 distinct
#define AS_FLOATS (TBM * AS_STRIDE)            // 5120
#define BS_FLOATS (TBK * BS_STRIDE)            // 2176
#define STAGE_FLOATS (AS_FLOATS + BS_FLOATS)   // 7296
#define TSMEM_BYTES (STAGE_FLOATS * 2 * 4 + TBM * 4)  // 59392

__device__ __forceinline__ void mma_tf32(float* c, const unsigned* a, const unsigned* b) {
    asm volatile(
        "mma.sync.aligned.m16n8k8.row.col.f32.tf32.tf32.f32 "
        "{%0,%1,%2,%3}, {%4,%5,%6,%7}, {%8,%9}, {%0,%1,%2,%3};"
        : "+f"(c[0]), "+f"(c[1]), "+f"(c[2]), "+f"(c[3])
        : "r"(a[0]), "r"(a[1]), "r"(a[2]), "r"(a[3]), "r"(b[0]), "r"(b[1]));
}

template <int MODE>
__device__ __forceinline__ float epi_val(float v, int col,
                                         const float* __restrict__ bias,
                                         const float* __restrict__ bias2) {
    if (MODE == MODE_QKV) {
        v += (col < 512) ? bias[col] : ((col < 1024) ? 0.f : bias2[col - 1024]);
    } else {
        v += bias[col];
        if (MODE == MODE_BIAS_GELU)
            v = 0.5f * v * (1.f + erff(v * 0.70710678118654752f));
    }
    return v;
}

template <int MODE>
__global__ __launch_bounds__(256, 1)
void tgemm_kernel(const float* __restrict__ A, const float* __restrict__ B,
                  float* __restrict__ C, int M, int N, int K,
                  const float* __restrict__ bias, const float* __restrict__ bias2) {
    extern __shared__ float sm[];
    float* Asm[2] = { sm,             sm + STAGE_FLOATS };
    float* Bsm[2] = { sm + AS_FLOATS, sm + STAGE_FLOATS + AS_FLOATS };
    int* srcOff = (int*)(sm + 2 * STAGE_FLOATS);

    const int tid = threadIdx.x;
    const int rowBase = blockIdx.y * TBM;
    const int colBase = blockIdx.x * TBN;

    {
        int r = rowBase + tid;
        srcOff[tid] = (MODE == MODE_QKV) ? qkv_src_row(r) * 512 : r * K;
    }
    __syncthreads();

    const int arow = tid >> 2;            // 0..63 (+64*i)
    const int acol = (tid & 3) << 2;      // 0,4,8,12

    const int warp = tid >> 5;
    const int wm = (warp >> 1) << 6;      // 0,64,128,192
    const int wn = (warp & 1) << 6;       // 0,64
    const int lane = tid & 31;
    const int g = lane >> 2, t4 = lane & 3;

    float acc[4][8][4];
    #pragma unroll
    for (int i = 0; i < 4; i++)
        #pragma unroll
        for (int j = 0; j < 8; j++)
            #pragma unroll
            for (int q = 0; q < 4; q++) acc[i][j][q] = 0.f;

    float4 pa[4], pb[2];

    // prologue: load k-tile 0
    #pragma unroll
    for (int i = 0; i < 4; i++)
        pa[i] = *(const float4*)(A + srcOff[arow + 64 * i] + acol);
    #pragma unroll
    for (int i = 0; i < 2; i++) {
        int j = tid + 256 * i;
        pb[i] = *(const float4*)(B + (size_t)(j >> 5) * N + colBase + ((j & 31) << 2));
    }
    #pragma unroll
    for (int i = 0; i < 4; i++)
        *(float4*)(Asm[0] + (arow + 64 * i) * AS_STRIDE + acol) = pa[i];
    #pragma unroll
    for (int i = 0; i < 2; i++) {
        int j = tid + 256 * i;
        *(float4*)(Bsm[0] + (j >> 5) * BS_STRIDE + ((j & 31) << 2)) = pb[i];
    }
    __syncthreads();

    const int KT = K / TBK;
    int st = 0;
    for (int kt = 0; kt < KT; kt++) {
        if (kt + 1 < KT) {
            int ko = (kt + 1) * TBK;
            #pragma unroll
            for (int i = 0; i < 4; i++)
                pa[i] = *(const float4*)(A + srcOff[arow + 64 * i] + ko + acol);
            #pragma unroll
            for (int i = 0; i < 2; i++) {
                int j = tid + 256 * i;
                pb[i] = *(const float4*)(B + (size_t)(ko + (j >> 5)) * N + colBase + ((j & 31) << 2));
            }
        }

        // compute on stage st
        const float* As = Asm[st];
        const float* Bs = Bsm[st];
        #pragma unroll
        for (int ks = 0; ks < 2; ks++) {
            unsigned af[4][4], bf[8][2];
            int k0 = ks * 8 + t4;
            #pragma unroll
            for (int i = 0; i < 4; i++) {
                const float* ap = As + (wm + i * 16 + g) * AS_STRIDE + k0;
                af[i][0] = __float_as_uint(ap[0]);
                af[i][1] = __float_as_uint(ap[8 * AS_STRIDE]);
                af[i][2] = __float_as_uint(ap[4]);
                af[i][3] = __float_as_uint(ap[8 * AS_STRIDE + 4]);
            }
            #pragma unroll
            for (int j = 0; j < 8; j++) {
                const float* bp = Bs + k0 * BS_STRIDE + wn + j * 8 + g;
                bf[j][0] = __float_as_uint(bp[0]);
                bf[j][1] = __float_as_uint(bp[4 * BS_STRIDE]);
            }
            #pragma unroll
            for (int i = 0; i < 4; i++)
                #pragma unroll
                for (int j = 0; j < 8; j++)
                    mma_tf32(acc[i][j], af[i], bf[j]);
        }

        if (kt + 1 < KT) {
            int ns = st ^ 1;
            #pragma unroll
            for (int i = 0; i < 4; i++)
                *(float4*)(Asm[ns] + (arow + 64 * i) * AS_STRIDE + acol) = pa[i];
            #pragma unroll
            for (int i = 0; i < 2; i++) {
                int j = tid + 256 * i;
                *(float4*)(Bsm[ns] + (j >> 5) * BS_STRIDE + ((j & 31) << 2)) = pb[i];
            }
        }
        __syncthreads();
        st ^= 1;
    }

    // epilogue
    #pragma unroll
    for (int i = 0; i < 4; i++) {
        int r0 = rowBase + wm + i * 16 + g;
        #pragma unroll
        for (int j = 0; j < 8; j++) {
            int c = colBase + wn + j * 8 + t4 * 2;
            float2 lo, hi;
            lo.x = epi_val<MODE>(acc[i][j][0], c,     bias, bias2);
            lo.y = epi_val<MODE>(acc[i][j][1], c + 1, bias, bias2);
            hi.x = epi_val<MODE>(acc[i][j][2], c,     bias, bias2);
            hi.y = epi_val<MODE>(acc[i][j][3], c + 1, bias, bias2);
            *(float2*)(C + (size_t)r0 * N + c) = lo;
            *(float2*)(C + (size_t)(r0 + 8) * N + c) = hi;
        }
    }
}

// ---------------- per-(window, head) attention ----------------
__global__ __launch_bounds__(256)
void attn_kernel(const float* __restrict__ mask,
                 const float* __restrict__ logit_scale) {
    int blk  = blockIdx.x;
    int win  = blk >> 4;
    int head = blk & 15;
    const int T = 256;
    __shared__ float qs[NTOKW * 32], ks[NTOKW * 32], vs[NTOKW * 32];
    __shared__ float S[NTOKW * NTOKW];
    __shared__ float rqn[NTOKW], rkn[NTOKW];
    int tid = threadIdx.x;

    size_t base = (size_t)win * NTOKW * 1536 + head * 32;
    for (int i = tid; i < NTOKW * 32; i += T) {
        int n = i >> 5, d = i & 31;
        size_t o = base + (size_t)n * 1536 + d;
        qs[i] = g_qkv[o];
        ks[i] = g_qkv[o + 512];
        vs[i] = g_qkv[o + 1024];
    }
    __syncthreads();

    if (tid < 2 * NTOKW) {
        int n = tid % NTOKW;
        const float* p = (tid < NTOKW) ? (qs + n * 32) : (ks + n * 32);
        float s = 0.f;
        #pragma unroll
        for (int d = 0; d < 32; d++) { float v = p[d]; s += v * v; }
        float inv = rsqrtf(s);
        if (tid < NTOKW) rqn[n] = inv; else rkn[n] = inv;
    }
    float scale = expf(fminf(logit_scale[head], 4.6051701859880914f)); // ln(100)
    __syncthreads();

    const float* bh = g_biasT + head * 2401;
    const float* mw = mask + (size_t)(win & 63) * 2401;
    for (int p = tid; p < 2401; p += T) {
        int n = p / NTOKW, m = p - n * NTOKW;
        const float* qp = qs + n * 32;
        const float* kp = ks + m * 32;
        float s = 0.f;
        #pragma unroll
        for (int d = 0; d < 32; d++) s += qp[d] * kp[d];
        S[p] = s * rqn[n] * rkn[m] * scale + bh[p] + mw[p];
    }
    __syncthreads();

    if (tid < NTOKW) {
        float* row = S + tid * NTOKW;
        float mx = row[0];
        for (int m = 1; m < NTOKW; m++) mx = fmaxf(mx, row[m]);
        float sum = 0.f;
        for (int m = 0; m < NTOKW; m++) { float e = expf(row[m] - mx); row[m] = e; sum += e; }
        float inv = 1.f / sum;
        for (int m = 0; m < NTOKW; m++) row[m] *= inv;
    }
    __syncthreads();

    for (int i = tid; i < NTOKW * 32; i += T) {
        int n = i >> 5, d = i & 31;
        const float* Pr = S + n * NTOKW;
        float s = 0.f;
        #pragma unroll
        for (int m = 0; m < NTOKW; m++) s += Pr[m] * vs[m * 32 + d];
        g_attnout[(size_t)(win * NTOKW + n) * CDIM + head * 32 + d] = s;
    }
}

// ---------------- LayerNorm + residual helpers ----------------
__device__ __forceinline__ void block_reduce2(float& s, float& ss) {
    __shared__ float red[32];
    int lane = threadIdx.x & 31, warp = threadIdx.x >> 5;
    #pragma unroll
    for (int o = 16; o > 0; o >>= 1) {
        s  += __shfl_down_sync(0xffffffffu, s,  o);
        ss += __shfl_down_sync(0xffffffffu, ss, o);
    }
    if (lane == 0) { red[warp] = s; red[warp + 16] = ss; }
    __syncthreads();
    if (threadIdx.x == 0) {
        float a = 0.f, b = 0.f;
        int nw = blockDim.x >> 5;
        for (int w = 0; w < nw; w++) { a += red[w]; b += red[w + 16]; }
        red[0] = a; red[16] = b;
    }
    __syncthreads();
    s = red[0]; ss = red[16];
    __syncthreads();
}

// x1[pixel] = x[pixel] + LN(proj[window-token for that pixel])
__global__ __launch_bounds__(128)
void post_attn_kernel(const float* __restrict__ x,
                      const float* __restrict__ g1, const float* __restrict__ b1) {
    int p = blockIdx.x;
    int b = p / 3136, rem = p - b * 3136;
    int h = rem / 56, w = rem - (rem / 56) * 56;
    int hs = h - 3; if (hs < 0) hs += 56;
    int ws = w - 3; if (ws < 0) ws += 56;
    int t = (b * 64 + (hs / 7) * 8 + (ws / 7)) * NTOKW + (hs % 7) * 7 + (ws % 7);
    const float* row = g_proj + (size_t)t * CDIM;
    float s = 0.f, ss = 0.f;
    for (int c = threadIdx.x; c < CDIM; c += blockDim.x) {
        float v = row[c]; s += v; ss += v * v;
    }
    block_reduce2(s, ss);
    float mu = s * (1.f / CDIM);
    float var = ss * (1.f / CDIM) - mu * mu;
    float rstd = rsqrtf(var + 1e-5f);
    const float* xr = x + (size_t)p * CDIM;
    float* o = g_x1 + (size_t)p * CDIM;
    for (int c = threadIdx.x; c < CDIM; c += blockDim.x)
        o[c] = xr[c] + (row[c] - mu) * rstd * g1[c] + b1[c];
}

// out[pixel] = x1[pixel] + LN(h2[pixel])
__global__ __launch_bounds__(128)
void final_kernel(const float* __restrict__ g2, const float* __restrict__ b2,
                  float* __restrict__ out) {
    int p = blockIdx.x;
    const float* row = g_h2 + (size_t)p * CDIM;
    float s = 0.f, ss = 0.f;
    for (int c = threadIdx.x; c < CDIM; c += blockDim.x) {
        float v = row[c]; s += v; ss += v * v;
    }
    block_reduce2(s, ss);
    float mu = s * (1.f / CDIM);
    float var = ss * (1.f / CDIM) - mu * mu;
    float rstd = rsqrtf(var + 1e-5f);
    const float* xr = g_x1 + (size_t)p * CDIM;
    float* o = out + (size_t)p * CDIM;
    for (int c = threadIdx.x; c < CDIM; c += blockDim.x)
        o[c] = xr[c] + (row[c] - mu) * rstd * g2[c] + b2[c];
}

// ---------------- launch ----------------
extern "C" void kernel_launch(void* const* d_in, const int* in_sizes, int n_in,
                              void* d_out, int out_size) {
    const float* x        = (const float*)d_in[0];
    const float* qkv_w    = (const float*)d_in[1];
    const float* q_bias   = (const float*)d_in[2];
    const float* v_bias   = (const float*)d_in[3];
    const float* proj_w   = (const float*)d_in[4];
    const float* proj_b   = (const float*)d_in[5];
    const float* lscale   = (const float*)d_in[6];
    const float* cpb_w1   = (const float*)d_in[7];
    const float* cpb_b1   = (const float*)d_in[8];
    const float* cpb_w2   = (const float*)d_in[9];
    const float* rct      = (const float*)d_in[10];
    const float* gamma1   = (const float*)d_in[11];
    const float* beta1    = (const float*)d_in[12];
    const float* gamma2   = (const float*)d_in[13];
    const float* beta2    = (const float*)d_in[14];
    const float* fc1_w    = (const float*)d_in[15];
    const float* fc1_b    = (const float*)d_in[16];
    const float* fc2_w    = (const float*)d_in[17];
    const float* fc2_b    = (const float*)d_in[18];
    const int*   rpi      = (const int*)d_in[19];
    const float* amask    = (const float*)d_in[20];
    float* out = (float*)d_out;

    float *p_qkv, *p_attn, *p_proj, *p_x1, *p_hid, *p_h2;
    cudaGetSymbolAddress((void**)&p_qkv,  g_qkv);
    cudaGetSymbolAddress((void**)&p_attn, g_attnout);
    cudaGetSymbolAddress((void**)&p_proj, g_proj);
    cudaGetSymbolAddress((void**)&p_x1,   g_x1);
    cudaGetSymbolAddress((void**)&p_hid,  g_hidden);
    cudaGetSymbolAddress((void**)&p_h2,   g_h2);

    cudaFuncSetAttribute(tgemm_kernel<MODE_QKV>,
                         cudaFuncAttributeMaxDynamicSharedMemorySize, TSMEM_BYTES);
    cudaFuncSetAttribute(tgemm_kernel<MODE_BIAS>,
                         cudaFuncAttributeMaxDynamicSharedMemorySize, TSMEM_BYTES);
    cudaFuncSetAttribute(tgemm_kernel<MODE_BIAS_GELU>,
                         cudaFuncAttributeMaxDynamicSharedMemorySize, TSMEM_BYTES);

    // 1. continuous position bias
    cpb_table_kernel<<<169, 512>>>(rct, cpb_w1, cpb_b1, cpb_w2);
    bias_expand_kernel<<<(16 * 2401 + 255) / 256, 256>>>(rpi);

    // 2. QKV GEMM (A gathered: roll + window partition fused)
    tgemm_kernel<MODE_QKV><<<dim3(1536 / TBN, TOK / TBM), 256, TSMEM_BYTES>>>(
        x, qkv_w, p_qkv, TOK, 1536, 512, q_bias, v_bias);

    // 3. windowed cosine attention
    attn_kernel<<<NWIN * NHEAD, 256>>>(amask, lscale);

    // 4. output projection
    tgemm_kernel<MODE_BIAS><<<dim3(CDIM / TBN, TOK / TBM), 256, TSMEM_BYTES>>>(
        p_attn, proj_w, p_proj, TOK, CDIM, CDIM, proj_b, nullptr);

    // 5. window reverse + un-roll + LN + residual  -> x1 (pixel order)
    post_attn_kernel<<<TOK, 128>>>(x, gamma1, beta1);

    // 6. MLP
    tgemm_kernel<MODE_BIAS_GELU><<<dim3(HID / TBN, TOK / TBM), 256, TSMEM_BYTES>>>(
        p_x1, fc1_w, p_hid, TOK, HID, 512, fc1_b, nullptr);
    tgemm_kernel<MODE_BIAS><<<dim3(CDIM / TBN, TOK / TBM), 256, TSMEM_BYTES>>>(
        p_hid, fc2_w, p_h2, TOK, CDIM, HID, fc2_b, nullptr);

    // 7. final LN + residual
    final_kernel<<<TOK, 128>>>(gamma2, beta2, out);
}

// round 4
// speedup vs baseline: 2.1985x; 1.2200x over previous
#include <cuda_runtime.h>
#include <cuda_fp16.h>
#include <math.h>
#include <stdint.h>

#define TOK   50176      // B*H*W tokens
#define CDIM  512
#define HID   2048
#define NHEAD 16
#define NTOKW 49         // tokens per window
#define NWIN  1024       // B * 64

// ---------------- scratch (device globals; no allocation) ----------------
__device__ float g_qkv    [(size_t)TOK * 1536];
__device__ float g_attnout[(size_t)TOK * CDIM];
__device__ float g_proj   [(size_t)TOK * CDIM];
__device__ float g_x1     [(size_t)TOK * CDIM];
__device__ float g_hidden [(size_t)TOK * HID];
__device__ float g_h2     [(size_t)TOK * CDIM];
__device__ float g_table  [169 * 16];
__device__ float g_biasT  [16 * 2401];
// transposed fp16 weights [N][K]
__device__ __half g_wt_qkv [1536 * 512];
__device__ __half g_wt_proj[512 * 512];
__device__ __half g_wt_fc1 [2048 * 512];
__device__ __half g_wt_fc2 [512 * 2048];

// ---------------- small helpers ----------------
__device__ __forceinline__ uint32_t smem_u32(const void* p) {
    uint32_t a;
    asm("{ .reg .u64 t; cvta.to.shared.u64 t, %1; cvt.u32.u64 %0, t; }" : "=r"(a) : "l"(p));
    return a;
}
__device__ __forceinline__ uint32_t pack2(float x, float y) {
    __half2 h = __floats2half2_rn(x, y);
    return *reinterpret_cast<uint32_t*>(&h);
}
__device__ __forceinline__ void ldsm4(uint32_t* r, uint32_t addr) {
    asm volatile("ldmatrix.sync.aligned.m8n8.x4.shared.b16 {%0,%1,%2,%3}, [%4];"
                 : "=r"(r[0]), "=r"(r[1]), "=r"(r[2]), "=r"(r[3]) : "r"(addr));
}
__device__ __forceinline__ void mma16816(float* c, const uint32_t* a, const uint32_t* b) {
    asm volatile("mma.sync.aligned.m16n8k16.row.col.f32.f16.f16.f32 "
                 "{%0,%1,%2,%3}, {%4,%5,%6,%7}, {%8,%9}, {%0,%1,%2,%3};"
                 : "+f"(c[0]), "+f"(c[1]), "+f"(c[2]), "+f"(c[3])
                 : "r"(a[0]), "r"(a[1]), "r"(a[2]), "r"(a[3]), "r"(b[0]), "r"(b[1]));
}

// ---------------- index helpers ----------------
// window-ordered token t -> pixel row in x (applies roll(-3,-3) + window partition)
__device__ __forceinline__ int qkv_src_row(int t) {
    int b   = t / 3136;
    int r5  = t - b * 3136;
    int win = r5 / NTOKW;
    int n   = r5 - win * NTOKW;
    int wh = win >> 3, ww = win & 7;
    int rr = n / 7,    cc = n - (n / 7) * 7;
    int hs = wh * 7 + rr, ws = ww * 7 + cc;
    int h = hs + 3; if (h >= 56) h -= 56;
    int w = ws + 3; if (w >= 56) w -= 56;
    return (b * 56 + h) * 56 + w;
}

// ---------------- weight transpose: src fp32 [K][N] -> dst fp16 [N][K] -----
__global__ void transpose_kernel(const float* __restrict__ S, __half* __restrict__ D,
                                 int K, int N) {
    __shared__ float t[32][33];
    int bx = blockIdx.x * 32, by = blockIdx.y * 32;
    int x = bx + threadIdx.x;
    #pragma unroll
    for (int i = 0; i < 32; i += 8)
        t[threadIdx.y + i][threadIdx.x] = S[(size_t)(by + threadIdx.y + i) * N + x];
    __syncthreads();
    int x2 = by + threadIdx.x;
    #pragma unroll
    for (int i = 0; i < 32; i += 8)
        D[(size_t)(bx + threadIdx.y + i) * K + x2] = __float2half_rn(t[threadIdx.x][threadIdx.y + i]);
}

// ---------------- CPB MLP: table[169][16] ----------------
__global__ void cpb_table_kernel(const float* __restrict__ rct,
                                 const float* __restrict__ w1,
                                 const float* __restrict__ b1,
                                 const float* __restrict__ w2) {
    int pos = blockIdx.x;
    float t0 = rct[pos * 2 + 0];
    float t1 = rct[pos * 2 + 1];
    __shared__ float hid[512];
    int j = threadIdx.x;
    float hv = t0 * w1[j] + t1 * w1[512 + j] + b1[j];
    hid[j] = fmaxf(hv, 0.f);
    __syncthreads();
    int warp = j >> 5, lane = j & 31;
    float s = 0.f;
    for (int jj = lane; jj < 512; jj += 32) s += hid[jj] * w2[jj * 16 + warp];
    #pragma unroll
    for (int o = 16; o > 0; o >>= 1) s += __shfl_down_sync(0xffffffffu, s, o);
    if (lane == 0) g_table[pos * 16 + warp] = s;
}

__global__ void bias_expand_kernel(const int* __restrict__ rpi) {
    int i = blockIdx.x * blockDim.x + threadIdx.x;
    if (i >= 16 * 2401) return;
    int h = i / 2401, nm = i - h * 2401;
    float v = g_table[rpi[nm] * 16 + h];
    g_biasT[i] = 16.f / (1.f + expf(-v));
}

// ---------------- fp16 tensor-core GEMM (mma.sync m16n8k16 + ldmatrix) -----
// C[M,N] = A[M,K] @ Wt[N,K]^T + epilogue.
// Block tile 128x128x32, 8 warps (2 m-groups x 4 n-groups), warp tile 64x32.
#define MODE_BIAS      0
#define MODE_QKV       1
#define MODE_BIAS_GELU 2

#define GBK 32
#define ROWB 80            // smem bytes per row: 64B data + 16B pad (conflict-free)
#define STAGE_B 20480      // 256 rows * 80B (128 A rows + 128 B rows)
#define BOFF 10240
#define HG_SMEM (2 * STAGE_B + 128 * 4)

template <int MODE>
__device__ __forceinline__ float epi_val(float v, int col,
                                         const float* __restrict__ bias,
                                         const float* __restrict__ bias2) {
    if (MODE == MODE_QKV) {
        v += (col < 512) ? bias[col] : ((col < 1024) ? 0.f : bias2[col - 1024]);
    } else {
        v += bias[col];
        if (MODE == MODE_BIAS_GELU)
            v = 0.5f * v * (1.f + erff(v * 0.70710678118654752f));
    }
    return v;
}

template <int MODE>
__global__ __launch_bounds__(256)
void hgemm_kernel(const float* __restrict__ A, const __half* __restrict__ Wt,
                  float* __restrict__ C, int M, int N, int K,
                  const float* __restrict__ bias, const float* __restrict__ bias2) {
    extern __shared__ char smc[];
    const uint32_t sb = smem_u32(smc);
    const int tid  = threadIdx.x;
    const int lane = tid & 31;
    const int wid  = tid >> 5;
    const int rowBase = blockIdx.y * 128;
    const int colBase = blockIdx.x * 128;
    int* srcOff = (int*)(smc + 2 * STAGE_B);

    if (tid < 128) {
        int r = rowBase + tid;
        srcOff[tid] = (MODE == MODE_QKV) ? qkv_src_row(r) * 512 : r * K;
    }
    __syncthreads();

    // ---- loader mapping: threads 0-127 -> A row tid; 128-255 -> B row tid-128
    const bool isA = tid < 128;
    const int  ldRow = tid & 127;
    const float*  gA = A  + (isA ? srcOff[ldRow] : 0);
    const __half* gB = Wt + (size_t)(colBase + ldRow) * K;
    const uint32_t rbase = (isA ? 0u : (uint32_t)BOFF) + (uint32_t)ldRow * ROWB;

    // ---- compute mapping: warp tile 64x32
    const int wm = (wid >> 2) * 64;        // 0, 64
    const int wn = (wid & 3) * 32;         // 0, 32, 64, 96

    float acc[4][4][4];
    #pragma unroll
    for (int m = 0; m < 4; m++)
        #pragma unroll
        for (int f = 0; f < 4; f++)
            #pragma unroll
            for (int q = 0; q < 4; q++) acc[m][f][q] = 0.f;

    const uint32_t aFragBase = (uint32_t)(wm + (lane & 15)) * ROWB + (uint32_t)(lane >> 4) * 16;
    const uint32_t bFragBase = (uint32_t)BOFF +
        (uint32_t)(wn + (lane & 7) + ((lane >> 4) & 1) * 8) * ROWB + (uint32_t)((lane >> 3) & 1) * 16;

    uint32_t h[16];
    // ---- prologue: tile 0
    if (isA) {
        #pragma unroll
        for (int i = 0; i < 8; i++) {
            float4 v = *(const float4*)(gA + i * 4);
            h[2 * i]     = pack2(v.x, v.y);
            h[2 * i + 1] = pack2(v.z, v.w);
        }
    } else {
        #pragma unroll
        for (int i = 0; i < 4; i++) {
            uint4 v = *(const uint4*)(gB + i * 8);
            h[4 * i] = v.x; h[4 * i + 1] = v.y; h[4 * i + 2] = v.z; h[4 * i + 3] = v.w;
        }
    }
    #pragma unroll
    for (int c = 0; c < 4; c++)
        *(uint4*)(smc + rbase + c * 16) = make_uint4(h[4 * c], h[4 * c + 1], h[4 * c + 2], h[4 * c + 3]);
    __syncthreads();

    const int KT = K / GBK;
    int st = 0;
    for (int kt = 0; kt < KT; kt++) {
        if (kt + 1 < KT) {
            int ko = (kt + 1) * GBK;
            if (isA) {
                #pragma unroll
                for (int i = 0; i < 8; i++) {
                    float4 v = *(const float4*)(gA + ko + i * 4);
                    h[2 * i]     = pack2(v.x, v.y);
                    h[2 * i + 1] = pack2(v.z, v.w);
                }
            } else {
                #pragma unroll
                for (int i = 0; i < 4; i++) {
                    uint4 v = *(const uint4*)(gB + ko + i * 8);
                    h[4 * i] = v.x; h[4 * i + 1] = v.y; h[4 * i + 2] = v.z; h[4 * i + 3] = v.w;
                }
            }
        }

        // ---- compute on stage st
        {
            const uint32_t soff = sb + (uint32_t)st * STAGE_B;
            #pragma unroll
            for (int ks = 0; ks < 2; ks++) {
                uint32_t a[4][4], bt0[4], bt1[4];
                #pragma unroll
                for (int m = 0; m < 4; m++)
                    ldsm4(a[m], soff + aFragBase + m * 16 * ROWB + ks * 32);
                ldsm4(bt0, soff + bFragBase + ks * 32);
                ldsm4(bt1, soff + bFragBase + 16 * ROWB + ks * 32);
                uint32_t bf[4][2] = {{bt0[0], bt0[1]}, {bt0[2], bt0[3]},
                                     {bt1[0], bt1[1]}, {bt1[2], bt1[3]}};
                #pragma unroll
                for (int m = 0; m < 4; m++)
                    #pragma unroll
                    for (int f = 0; f < 4; f++)
                        mma16816(acc[m][f], a[m], bf[f]);
            }
        }

        if (kt + 1 < KT) {
            char* dst = smc + (st ^ 1) * STAGE_B + rbase;
            #pragma unroll
            for (int c = 0; c < 4; c++)
                *(uint4*)(dst + c * 16) = make_uint4(h[4 * c], h[4 * c + 1], h[4 * c + 2], h[4 * c + 3]);
        }
        __syncthreads();
        st ^= 1;
    }

    // ---- epilogue: direct register -> gmem
    #pragma unroll
    for (int m = 0; m < 4; m++) {
        int r0 = rowBase + wm + m * 16 + (lane >> 2);
        #pragma unroll
        for (int f = 0; f < 4; f++) {
            int c = colBase + wn + f * 8 + (lane & 3) * 2;
            float2 lo, hi;
            lo.x = epi_val<MODE>(acc[m][f][0], c,     bias, bias2);
            lo.y = epi_val<MODE>(acc[m][f][1], c + 1, bias, bias2);
            hi.x = epi_val<MODE>(acc[m][f][2], c,     bias, bias2);
            hi.y = epi_val<MODE>(acc[m][f][3], c + 1, bias, bias2);
            *(float2*)(C + (size_t)r0 * N + c) = lo;
            *(float2*)(C + (size_t)(r0 + 8) * N + c) = hi;
        }
    }
}

// ---------------- per-(window, head) attention ----------------
__global__ __launch_bounds__(256)
void attn_kernel(const float* __restrict__ mask,
                 const float* __restrict__ logit_scale) {
    int blk  = blockIdx.x;
    int win  = blk >> 4;
    int head = blk & 15;
    const int T = 256;
    __shared__ float qs[NTOKW * 32], ks[NTOKW * 32], vs[NTOKW * 32];
    __shared__ float S[NTOKW * NTOKW];
    __shared__ float rqn[NTOKW], rkn[NTOKW];
    int tid = threadIdx.x;

    size_t base = (size_t)win * NTOKW * 1536 + head * 32;
    for (int i = tid; i < NTOKW * 32; i += T) {
        int n = i >> 5, d = i & 31;
        size_t o = base + (size_t)n * 1536 + d;
        qs[i] = g_qkv[o];
        ks[i] = g_qkv[o + 512];
        vs[i] = g_qkv[o + 1024];
    }
    __syncthreads();

    if (tid < 2 * NTOKW) {
        int n = tid % NTOKW;
        const float* p = (tid < NTOKW) ? (qs + n * 32) : (ks + n * 32);
        float s = 0.f;
        #pragma unroll
        for (int d = 0; d < 32; d++) { float v = p[d]; s += v * v; }
        float inv = rsqrtf(s);
        if (tid < NTOKW) rqn[n] = inv; else rkn[n] = inv;
    }
    float scale = expf(fminf(logit_scale[head], 4.6051701859880914f));
    __syncthreads();

    const float* bh = g_biasT + head * 2401;
    const float* mw = mask + (size_t)(win & 63) * 2401;
    for (int p = tid; p < 2401; p += T) {
        int n = p / NTOKW, m = p - n * NTOKW;
        const float* qp = qs + n * 32;
        const float* kp = ks + m * 32;
        float s = 0.f;
        #pragma unroll
        for (int d = 0; d < 32; d++) s += qp[d] * kp[d];
        S[p] = s * rqn[n] * rkn[m] * scale + bh[p] + mw[p];
    }
    __syncthreads();

    if (tid < NTOKW) {
        float* row = S + tid * NTOKW;
        float mx = row[0];
        for (int m = 1; m < NTOKW; m++) mx = fmaxf(mx, row[m]);
        float sum = 0.f;
        for (int m = 0; m < NTOKW; m++) { float e = expf(row[m] - mx); row[m] = e; sum += e; }
        float inv = 1.f / sum;
        for (int m = 0; m < NTOKW; m++) row[m] *= inv;
    }
    __syncthreads();

    for (int i = tid; i < NTOKW * 32; i += T) {
        int n = i >> 5, d = i & 31;
        const float* Pr = S + n * NTOKW;
        float s = 0.f;
        #pragma unroll
        for (int m = 0; m < NTOKW; m++) s += Pr[m] * vs[m * 32 + d];
        g_attnout[(size_t)(win * NTOKW + n) * CDIM + head * 32 + d] = s;
    }
}

// ---------------- LayerNorm + residual helpers ----------------
__device__ __forceinline__ void block_reduce2(float& s, float& ss) {
    __shared__ float red[32];
    int lane = threadIdx.x & 31, warp = threadIdx.x >> 5;
    #pragma unroll
    for (int o = 16; o > 0; o >>= 1) {
        s  += __shfl_down_sync(0xffffffffu, s,  o);
        ss += __shfl_down_sync(0xffffffffu, ss, o);
    }
    if (lane == 0) { red[warp] = s; red[warp + 16] = ss; }
    __syncthreads();
    if (threadIdx.x == 0) {
        float a = 0.f, b = 0.f;
        int nw = blockDim.x >> 5;
        for (int w = 0; w < nw; w++) { a += red[w]; b += red[w + 16]; }
        red[0] = a; red[16] = b;
    }
    __syncthreads();
    s = red[0]; ss = red[16];
    __syncthreads();
}

__global__ __launch_bounds__(128)
void post_attn_kernel(const float* __restrict__ x,
                      const float* __restrict__ g1, const float* __restrict__ b1) {
    int p = blockIdx.x;
    int b = p / 3136, rem = p - b * 3136;
    int h = rem / 56, w = rem - (rem / 56) * 56;
    int hs = h - 3; if (hs < 0) hs += 56;
    int ws = w - 3; if (ws < 0) ws += 56;
    int t = (b * 64 + (hs / 7) * 8 + (ws / 7)) * NTOKW + (hs % 7) * 7 + (ws % 7);
    const float* row = g_proj + (size_t)t * CDIM;
    float s = 0.f, ss = 0.f;
    for (int c = threadIdx.x; c < CDIM; c += blockDim.x) {
        float v = row[c]; s += v; ss += v * v;
    }
    block_reduce2(s, ss);
    float mu = s * (1.f / CDIM);
    float var = ss * (1.f / CDIM) - mu * mu;
    float rstd = rsqrtf(var + 1e-5f);
    const float* xr = x + (size_t)p * CDIM;
    float* o = g_x1 + (size_t)p * CDIM;
    for (int c = threadIdx.x; c < CDIM; c += blockDim.x)
        o[c] = xr[c] + (row[c] - mu) * rstd * g1[c] + b1[c];
}

__global__ __launch_bounds__(128)
void final_kernel(const float* __restrict__ g2, const float* __restrict__ b2,
                  float* __restrict__ out) {
    int p = blockIdx.x;
    const float* row = g_h2 + (size_t)p * CDIM;
    float s = 0.f, ss = 0.f;
    for (int c = threadIdx.x; c < CDIM; c += blockDim.x) {
        float v = row[c]; s += v; ss += v * v;
    }
    block_reduce2(s, ss);
    float mu = s * (1.f / CDIM);
    float var = ss * (1.f / CDIM) - mu * mu;
    float rstd = rsqrtf(var + 1e-5f);
    const float* xr = g_x1 + (size_t)p * CDIM;
    float* o = out + (size_t)p * CDIM;
    for (int c = threadIdx.x; c < CDIM; c += blockDim.x)
        o[c] = xr[c] + (row[c] - mu) * rstd * g2[c] + b2[c];
}

// ---------------- launch ----------------
extern "C" void kernel_launch(void* const* d_in, const int* in_sizes, int n_in,
                              void* d_out, int out_size) {
    const float* x        = (const float*)d_in[0];
    const float* qkv_w    = (const float*)d_in[1];
    const float* q_bias   = (const float*)d_in[2];
    const float* v_bias   = (const float*)d_in[3];
    const float* proj_w   = (const float*)d_in[4];
    const float* proj_b   = (const float*)d_in[5];
    const float* lscale   = (const float*)d_in[6];
    const float* cpb_w1   = (const float*)d_in[7];
    const float* cpb_b1   = (const float*)d_in[8];
    const float* cpb_w2   = (const float*)d_in[9];
    const float* rct      = (const float*)d_in[10];
    const float* gamma1   = (const float*)d_in[11];
    const float* beta1    = (const float*)d_in[12];
    const float* gamma2   = (const float*)d_in[13];
    const float* beta2    = (const float*)d_in[14];
    const float* fc1_w    = (const float*)d_in[15];
    const float* fc1_b    = (const float*)d_in[16];
    const float* fc2_w    = (const float*)d_in[17];
    const float* fc2_b    = (const float*)d_in[18];
    const int*   rpi      = (const int*)d_in[19];
    const float* amask    = (const float*)d_in[20];
    float* out = (float*)d_out;

    float *p_qkv, *p_attn, *p_proj, *p_x1, *p_hid, *p_h2;
    __half *wt_qkv, *wt_proj, *wt_fc1, *wt_fc2;
    cudaGetSymbolAddress((void**)&p_qkv,   g_qkv);
    cudaGetSymbolAddress((void**)&p_attn,  g_attnout);
    cudaGetSymbolAddress((void**)&p_proj,  g_proj);
    cudaGetSymbolAddress((void**)&p_x1,    g_x1);
    cudaGetSymbolAddress((void**)&p_hid,   g_hidden);
    cudaGetSymbolAddress((void**)&p_h2,    g_h2);
    cudaGetSymbolAddress((void**)&wt_qkv,  g_wt_qkv);
    cudaGetSymbolAddress((void**)&wt_proj, g_wt_proj);
    cudaGetSymbolAddress((void**)&wt_fc1,  g_wt_fc1);
    cudaGetSymbolAddress((void**)&wt_fc2,  g_wt_fc2);

    cudaFuncSetAttribute(hgemm_kernel<MODE_QKV>,
                         cudaFuncAttributeMaxDynamicSharedMemorySize, HG_SMEM);
    cudaFuncSetAttribute(hgemm_kernel<MODE_BIAS>,
                         cudaFuncAttributeMaxDynamicSharedMemorySize, HG_SMEM);
    cudaFuncSetAttribute(hgemm_kernel<MODE_BIAS_GELU>,
                         cudaFuncAttributeMaxDynamicSharedMemorySize, HG_SMEM);

    // 0. weight transposes + fp16 convert: [K][N] fp32 -> [N][K] fp16
    transpose_kernel<<<dim3(1536 / 32, 512 / 32), dim3(32, 8)>>>(qkv_w, wt_qkv, 512, 1536);
    transpose_kernel<<<dim3(512 / 32, 512 / 32),  dim3(32, 8)>>>(proj_w, wt_proj, 512, 512);
    transpose_kernel<<<dim3(2048 / 32, 512 / 32), dim3(32, 8)>>>(fc1_w, wt_fc1, 512, 2048);
    transpose_kernel<<<dim3(512 / 32, 2048 / 32), dim3(32, 8)>>>(fc2_w, wt_fc2, 2048, 512);

    // 1. continuous position bias
    cpb_table_kernel<<<169, 512>>>(rct, cpb_w1, cpb_b1, cpb_w2);
    bias_expand_kernel<<<(16 * 2401 + 255) / 256, 256>>>(rpi);

    // 2. QKV GEMM (A gathered: roll + window partition fused)
    hgemm_kernel<MODE_QKV><<<dim3(1536 / 128, TOK / 128), 256, HG_SMEM>>>(
        x, wt_qkv, p_qkv, TOK, 1536, 512, q_bias, v_bias);

    // 3. windowed cosine attention
    attn_kernel<<<NWIN * NHEAD, 256>>>(amask, lscale);

    // 4. output projection
    hgemm_kernel<MODE_BIAS><<<dim3(CDIM / 128, TOK / 128), 256, HG_SMEM>>>(
        p_attn, wt_proj, p_proj, TOK, CDIM, CDIM, proj_b, nullptr);

    // 5. window reverse + un-roll + LN + residual  -> x1 (pixel order)
    post_attn_kernel<<<TOK, 128>>>(x, gamma1, beta1);

    // 6. MLP
    hgemm_kernel<MODE_BIAS_GELU><<<dim3(HID / 128, TOK / 128), 256, HG_SMEM>>>(
        p_x1, wt_fc1, p_hid, TOK, HID, 512, fc1_b, nullptr);
    hgemm_kernel<MODE_BIAS><<<dim3(CDIM / 128, TOK / 128), 256, HG_SMEM>>>(
        p_hid, wt_fc2, p_h2, TOK, CDIM, HID, fc2_b, nullptr);

    // 7. final LN + residual
    final_kernel<<<TOK, 128>>>(gamma2, beta2, out);
}

// round 5
// speedup vs baseline: 3.0562x; 1.3901x over previous
#include <cuda_runtime.h>
#include <cuda_fp16.h>
#include <math.h>
#include <stdint.h>

#define TOK   50176      // B*H*W tokens
#define CDIM  512
#define HID   2048
#define NHEAD 16
#define NTOKW 49         // tokens per window
#define NWIN  1024       // B * 64

// ---------------- scratch (device globals; no allocation) ----------------
__device__ __half g_xw16  [(size_t)TOK * CDIM];   // window-ordered x, fp16
__device__ float  g_qkv   [(size_t)TOK * 1536];
__device__ __half g_attn16[(size_t)TOK * CDIM];
__device__ float  g_proj  [(size_t)TOK * CDIM];
__device__ float  g_x1    [(size_t)TOK * CDIM];
__device__ __half g_x1h   [(size_t)TOK * CDIM];
__device__ __half g_hid16 [(size_t)TOK * HID];
__device__ float  g_h2    [(size_t)TOK * CDIM];
__device__ float  g_table [169 * 16];
__device__ float  g_biasT [16 * 2401];
// transposed fp16 weights [N][K]
__device__ __half g_wt_qkv [1536 * 512];
__device__ __half g_wt_proj[512 * 512];
__device__ __half g_wt_fc1 [2048 * 512];
__device__ __half g_wt_fc2 [512 * 2048];

// ---------------- small helpers ----------------
__device__ __forceinline__ uint32_t smem_u32(const void* p) {
    uint32_t a;
    asm("{ .reg .u64 t; cvta.to.shared.u64 t, %1; cvt.u32.u64 %0, t; }" : "=r"(a) : "l"(p));
    return a;
}
__device__ __forceinline__ void ldsm4(uint32_t* r, uint32_t addr) {
    asm volatile("ldmatrix.sync.aligned.m8n8.x4.shared.b16 {%0,%1,%2,%3}, [%4];"
                 : "=r"(r[0]), "=r"(r[1]), "=r"(r[2]), "=r"(r[3]) : "r"(addr));
}
__device__ __forceinline__ void mma16816(float* c, const uint32_t* a, const uint32_t* b) {
    asm volatile("mma.sync.aligned.m16n8k16.row.col.f32.f16.f16.f32 "
                 "{%0,%1,%2,%3}, {%4,%5,%6,%7}, {%8,%9}, {%0,%1,%2,%3};"
                 : "+f"(c[0]), "+f"(c[1]), "+f"(c[2]), "+f"(c[3])
                 : "r"(a[0]), "r"(a[1]), "r"(a[2]), "r"(a[3]), "r"(b[0]), "r"(b[1]));
}
__device__ __forceinline__ void cp16(uint32_t dst, const void* src) {
    asm volatile("cp.async.cg.shared.global [%0], [%1], 16;"
                 :: "r"(dst), "l"(__cvta_generic_to_global(src)) : "memory");
}
#define CP_COMMIT() asm volatile("cp.async.commit_group;" ::: "memory")
#define CP_WAIT2()  asm volatile("cp.async.wait_group 2;" ::: "memory")

// ---------------- index helpers ----------------
// window-ordered token t -> pixel row in x (applies roll(-3,-3) + window partition)
__device__ __forceinline__ int qkv_src_row(int t) {
    int b   = t / 3136;
    int r5  = t - b * 3136;
    int win = r5 / NTOKW;
    int n   = r5 - win * NTOKW;
    int wh = win >> 3, ww = win & 7;
    int rr = n / 7,    cc = n - (n / 7) * 7;
    int hs = wh * 7 + rr, ws = ww * 7 + cc;
    int h = hs + 3; if (h >= 56) h -= 56;
    int w = ws + 3; if (w >= 56) w -= 56;
    return (b * 56 + h) * 56 + w;
}

// ---------------- gather x into window order, fp16 ----------------
__global__ __launch_bounds__(256)
void gather_x_kernel(const float* __restrict__ x) {
    int token = blockIdx.x * 2 + (threadIdx.x >> 7);
    int i4 = threadIdx.x & 127;
    int src = qkv_src_row(token);
    float4 v = ((const float4*)x)[(size_t)src * 128 + i4];
    __half2 h0 = __floats2half2_rn(v.x, v.y);
    __half2 h1 = __floats2half2_rn(v.z, v.w);
    __half2* o = (__half2*)g_xw16 + (size_t)token * 256 + i4 * 2;
    o[0] = h0; o[1] = h1;
}

// ---------------- weight transpose: src fp32 [K][N] -> dst fp16 [N][K] -----
__global__ void transpose_kernel(const float* __restrict__ S, __half* __restrict__ D,
                                 int K, int N) {
    __shared__ float t[32][33];
    int bx = blockIdx.x * 32, by = blockIdx.y * 32;
    int x = bx + threadIdx.x;
    #pragma unroll
    for (int i = 0; i < 32; i += 8)
        t[threadIdx.y + i][threadIdx.x] = S[(size_t)(by + threadIdx.y + i) * N + x];
    __syncthreads();
    int x2 = by + threadIdx.x;
    #pragma unroll
    for (int i = 0; i < 32; i += 8)
        D[(size_t)(bx + threadIdx.y + i) * K + x2] = __float2half_rn(t[threadIdx.x][threadIdx.y + i]);
}

// ---------------- CPB MLP: table[169][16] ----------------
__global__ void cpb_table_kernel(const float* __restrict__ rct,
                                 const float* __restrict__ w1,
                                 const float* __restrict__ b1,
                                 const float* __restrict__ w2) {
    int pos = blockIdx.x;
    float t0 = rct[pos * 2 + 0];
    float t1 = rct[pos * 2 + 1];
    __shared__ float hid[512];
    int j = threadIdx.x;
    float hv = t0 * w1[j] + t1 * w1[512 + j] + b1[j];
    hid[j] = fmaxf(hv, 0.f);
    __syncthreads();
    int warp = j >> 5, lane = j & 31;
    float s = 0.f;
    for (int jj = lane; jj < 512; jj += 32) s += hid[jj] * w2[jj * 16 + warp];
    #pragma unroll
    for (int o = 16; o > 0; o >>= 1) s += __shfl_down_sync(0xffffffffu, s, o);
    if (lane == 0) g_table[pos * 16 + warp] = s;
}

__global__ void bias_expand_kernel(const int* __restrict__ rpi) {
    int i = blockIdx.x * blockDim.x + threadIdx.x;
    if (i >= 16 * 2401) return;
    int h = i / 2401, nm = i - h * 2401;
    float v = g_table[rpi[nm] * 16 + h];
    g_biasT[i] = 16.f / (1.f + expf(-v));
}

// ---------------- fp16 tensor-core GEMM, cp.async 3-stage, BK=64 ----------
// C[M,N] = A[M,K] @ Wt[N,K]^T + epilogue. Block 128x128x64, 8 warps.
#define MODE_BIAS      0
#define MODE_QKV       1
#define MODE_GELU_H    2   // GELU + fp16 output

#define ROWB   144         // 128B data + 16B pad
#define STAGE  (256 * ROWB)            // 36864 B (A 128 rows + B 128 rows)
#define HG_SMEM (3 * STAGE)            // 110592 B

template <int MODE>
__global__ __launch_bounds__(256, 2)
void hgemm_kernel(const __half* __restrict__ A, const __half* __restrict__ Wt,
                  void* __restrict__ Cv, int M, int N, int K,
                  const float* __restrict__ bias, const float* __restrict__ bias2) {
    extern __shared__ char smc[];
    const uint32_t sb = smem_u32(smc);
    const int tid  = threadIdx.x;
    const int lane = tid & 31;
    const int wid  = tid >> 5;
    const int rowBase = blockIdx.y * 128;
    const int colBase = blockIdx.x * 128;

    // loader mapping: thread -> (row 0..127, half 0/1), 64B each for A and B
    const int ldRow  = tid >> 1;
    const int ldHalf = tid & 1;
    const __half* gA = A  + (size_t)(rowBase + ldRow) * K + ldHalf * 32;
    const __half* gB = Wt + (size_t)(colBase + ldRow) * K + ldHalf * 32;
    const uint32_t dstA = sb + (uint32_t)ldRow * ROWB + ldHalf * 64;
    const uint32_t dstB = dstA + 128 * ROWB;

    // compute mapping: warp tile 64x32
    const int wm = (wid >> 2) * 64;
    const int wn = (wid & 3) * 32;
    const uint32_t aFragBase = sb + (uint32_t)(wm + (lane & 15)) * ROWB + (uint32_t)(lane >> 4) * 16;
    const uint32_t bFragBase = sb + 128u * ROWB +
        (uint32_t)(wn + (lane & 7) + ((lane >> 4) & 1) * 8) * ROWB + (uint32_t)((lane >> 3) & 1) * 16;

    float acc[4][4][4];
    #pragma unroll
    for (int m = 0; m < 4; m++)
        #pragma unroll
        for (int f = 0; f < 4; f++)
            #pragma unroll
            for (int q = 0; q < 4; q++) acc[m][f][q] = 0.f;

    const int KT = K / 64;

    // prologue: stages 0,1,2
    #pragma unroll
    for (int s = 0; s < 3; s++) {
        #pragma unroll
        for (int j = 0; j < 4; j++) {
            cp16(dstA + s * STAGE + j * 16, gA + s * 64 + j * 8);
            cp16(dstB + s * STAGE + j * 16, gB + s * 64 + j * 8);
        }
        CP_COMMIT();
    }

    for (int kt = 0; kt < KT; kt++) {
        const uint32_t stOff = (uint32_t)(kt % 3) * STAGE;
        CP_WAIT2();
        __syncthreads();

        #pragma unroll
        for (int ks = 0; ks < 4; ks++) {
            uint32_t a[4][4], bt0[4], bt1[4];
            #pragma unroll
            for (int m = 0; m < 4; m++)
                ldsm4(a[m], stOff + aFragBase + m * 16 * ROWB + ks * 32);
            ldsm4(bt0, stOff + bFragBase + ks * 32);
            ldsm4(bt1, stOff + bFragBase + 16 * ROWB + ks * 32);
            uint32_t bf[4][2] = {{bt0[0], bt0[1]}, {bt0[2], bt0[3]},
                                 {bt1[0], bt1[1]}, {bt1[2], bt1[3]}};
            #pragma unroll
            for (int m = 0; m < 4; m++)
                #pragma unroll
                for (int f = 0; f < 4; f++)
                    mma16816(acc[m][f], a[m], bf[f]);
        }
        __syncthreads();

        if (kt + 3 < KT) {
            #pragma unroll
            for (int j = 0; j < 4; j++) {
                cp16(dstA + stOff + j * 16, gA + (kt + 3) * 64 + j * 8);
                cp16(dstB + stOff + j * 16, gB + (kt + 3) * 64 + j * 8);
            }
        }
        CP_COMMIT();
    }

    // epilogue
    #pragma unroll
    for (int m = 0; m < 4; m++) {
        int r0 = rowBase + wm + m * 16 + (lane >> 2);
        #pragma unroll
        for (int f = 0; f < 4; f++) {
            int c = colBase + wn + f * 8 + (lane & 3) * 2;
            float v0 = acc[m][f][0], v1 = acc[m][f][1];
            float v2 = acc[m][f][2], v3 = acc[m][f][3];
            if (MODE == MODE_QKV) {
                float b0 = (c < 512) ? bias[c] : ((c < 1024) ? 0.f : bias2[c - 1024]);
                float b1 = (c + 1 < 512) ? bias[c + 1] : ((c + 1 < 1024) ? 0.f : bias2[c + 1 - 1024]);
                v0 += b0; v1 += b1; v2 += b0; v3 += b1;
            } else {
                v0 += bias[c]; v1 += bias[c + 1]; v2 += bias[c]; v3 += bias[c + 1];
            }
            if (MODE == MODE_GELU_H) {
                v0 = 0.5f * v0 * (1.f + erff(v0 * 0.70710678118654752f));
                v1 = 0.5f * v1 * (1.f + erff(v1 * 0.70710678118654752f));
                v2 = 0.5f * v2 * (1.f + erff(v2 * 0.70710678118654752f));
                v3 = 0.5f * v3 * (1.f + erff(v3 * 0.70710678118654752f));
                __half* C = (__half*)Cv;
                *(__half2*)(C + (size_t)r0 * N + c)       = __floats2half2_rn(v0, v1);
                *(__half2*)(C + (size_t)(r0 + 8) * N + c) = __floats2half2_rn(v2, v3);
            } else {
                float* C = (float*)Cv;
                *(float2*)(C + (size_t)r0 * N + c)       = make_float2(v0, v1);
                *(float2*)(C + (size_t)(r0 + 8) * N + c) = make_float2(v2, v3);
            }
        }
    }
}

// ---------------- per-(window, head) attention ----------------
__global__ __launch_bounds__(256)
void attn_kernel(const float* __restrict__ mask,
                 const float* __restrict__ logit_scale) {
    int blk  = blockIdx.x;
    int win  = blk >> 4;
    int head = blk & 15;
    __shared__ float qs[NTOKW * 32], ks[NTOKW * 32], vs[NTOKW * 32];
    __shared__ float S[NTOKW * NTOKW];
    __shared__ float rqn[NTOKW], rkn[NTOKW];
    int tid = threadIdx.x;
    int lane = tid & 31, w = tid >> 5;

    size_t base = (size_t)win * NTOKW * 1536 + head * 32;
    for (int i = tid; i < NTOKW * 8; i += 256) {
        int n = i >> 3, d4 = i & 7;
        const float* src = g_qkv + base + (size_t)n * 1536;
        ((float4*)qs)[i] = ((const float4*)src)[d4];
        ((float4*)ks)[i] = ((const float4*)(src + 512))[d4];
        ((float4*)vs)[i] = ((const float4*)(src + 1024))[d4];
    }
    __syncthreads();

    if (tid < 2 * NTOKW) {
        int n = tid % NTOKW;
        const float* p = (tid < NTOKW) ? (qs + n * 32) : (ks + n * 32);
        float s = 0.f;
        #pragma unroll
        for (int d = 0; d < 32; d++) { float v = p[d]; s += v * v; }
        float inv = rsqrtf(s);
        if (tid < NTOKW) rqn[n] = inv; else rkn[n] = inv;
    }
    float scale = expf(fminf(logit_scale[head], 4.6051701859880914f));
    __syncthreads();

    const float* bh = g_biasT + head * 2401;
    const float* mw = mask + (size_t)(win & 63) * 2401;
    for (int p = tid; p < 2401; p += 256) {
        int n = p / NTOKW, m = p - n * NTOKW;
        const float* qp = qs + n * 32;
        const float* kp = ks + m * 32;
        float s = 0.f;
        #pragma unroll
        for (int d = 0; d < 32; d++) s += qp[d] * kp[d];
        S[p] = s * rqn[n] * rkn[m] * scale + bh[p] + mw[p];
    }
    __syncthreads();

    // warp-parallel softmax: warp w handles rows w, w+8, ...
    for (int r = w; r < NTOKW; r += 8) {
        float* row = S + r * NTOKW;
        float v0 = row[lane];
        float v1 = (lane < 17) ? row[32 + lane] : -1e30f;
        float mx = fmaxf(v0, v1);
        #pragma unroll
        for (int o = 16; o > 0; o >>= 1) mx = fmaxf(mx, __shfl_xor_sync(0xffffffffu, mx, o));
        float e0 = __expf(v0 - mx);
        float e1 = (lane < 17) ? __expf(v1 - mx) : 0.f;
        float s = e0 + e1;
        #pragma unroll
        for (int o = 16; o > 0; o >>= 1) s += __shfl_xor_sync(0xffffffffu, s, o);
        float inv = 1.f / s;
        row[lane] = e0 * inv;
        if (lane < 17) row[32 + lane] = e1 * inv;
    }
    __syncthreads();

    for (int i = tid; i < NTOKW * 32; i += 256) {
        int n = i >> 5, d = i & 31;
        const float* Pr = S + n * NTOKW;
        float s = 0.f;
        #pragma unroll
        for (int m = 0; m < NTOKW; m++) s += Pr[m] * vs[m * 32 + d];
        g_attn16[(size_t)(win * NTOKW + n) * CDIM + head * 32 + d] = __float2half_rn(s);
    }
}

// ---------------- LN kernels: warp per row ----------------
__global__ __launch_bounds__(256)
void post_attn_kernel(const float* __restrict__ x,
                      const float* __restrict__ g1, const float* __restrict__ b1) {
    int lane = threadIdx.x & 31;
    int p = blockIdx.x * 8 + (threadIdx.x >> 5);
    int b = p / 3136, rem = p - b * 3136;
    int h = rem / 56, w = rem - (rem / 56) * 56;
    int hs = h - 3; if (hs < 0) hs += 56;
    int ws = w - 3; if (ws < 0) ws += 56;
    int t = (b * 64 + (hs / 7) * 8 + (ws / 7)) * NTOKW + (hs % 7) * 7 + (ws % 7);

    const float4* row = (const float4*)(g_proj + (size_t)t * CDIM);
    float4 v[4];
    float s = 0.f, ss = 0.f;
    #pragma unroll
    for (int k = 0; k < 4; k++) {
        v[k] = row[lane + k * 32];
        s  += v[k].x + v[k].y + v[k].z + v[k].w;
        ss += v[k].x * v[k].x + v[k].y * v[k].y + v[k].z * v[k].z + v[k].w * v[k].w;
    }
    #pragma unroll
    for (int o = 16; o > 0; o >>= 1) {
        s  += __shfl_xor_sync(0xffffffffu, s,  o);
        ss += __shfl_xor_sync(0xffffffffu, ss, o);
    }
    float mu = s * (1.f / CDIM);
    float rstd = rsqrtf(ss * (1.f / CDIM) - mu * mu + 1e-5f);
    const float4* xr = (const float4*)(x + (size_t)p * CDIM);
    float4* o1 = (float4*)(g_x1 + (size_t)p * CDIM);
    __half2* oh = (__half2*)(g_x1h + (size_t)p * CDIM);
    #pragma unroll
    for (int k = 0; k < 4; k++) {
        int c = (lane + k * 32) * 4;
        float4 xv = xr[lane + k * 32];
        float4 o;
        o.x = xv.x + (v[k].x - mu) * rstd * g1[c + 0] + b1[c + 0];
        o.y = xv.y + (v[k].y - mu) * rstd * g1[c + 1] + b1[c + 1];
        o.z = xv.z + (v[k].z - mu) * rstd * g1[c + 2] + b1[c + 2];
        o.w = xv.w + (v[k].w - mu) * rstd * g1[c + 3] + b1[c + 3];
        o1[lane + k * 32] = o;
        oh[(lane + k * 32) * 2 + 0] = __floats2half2_rn(o.x, o.y);
        oh[(lane + k * 32) * 2 + 1] = __floats2half2_rn(o.z, o.w);
    }
}

__global__ __launch_bounds__(256)
void final_kernel(const float* __restrict__ g2, const float* __restrict__ b2,
                  float* __restrict__ out) {
    int lane = threadIdx.x & 31;
    int p = blockIdx.x * 8 + (threadIdx.x >> 5);
    const float4* row = (const float4*)(g_h2 + (size_t)p * CDIM);
    float4 v[4];
    float s = 0.f, ss = 0.f;
    #pragma unroll
    for (int k = 0; k < 4; k++) {
        v[k] = row[lane + k * 32];
        s  += v[k].x + v[k].y + v[k].z + v[k].w;
        ss += v[k].x * v[k].x + v[k].y * v[k].y + v[k].z * v[k].z + v[k].w * v[k].w;
    }
    #pragma unroll
    for (int o = 16; o > 0; o >>= 1) {
        s  += __shfl_xor_sync(0xffffffffu, s,  o);
        ss += __shfl_xor_sync(0xffffffffu, ss, o);
    }
    float mu = s * (1.f / CDIM);
    float rstd = rsqrtf(ss * (1.f / CDIM) - mu * mu + 1e-5f);
    const float4* xr = (const float4*)(g_x1 + (size_t)p * CDIM);
    float4* o1 = (float4*)(out + (size_t)p * CDIM);
    #pragma unroll
    for (int k = 0; k < 4; k++) {
        int c = (lane + k * 32) * 4;
        float4 xv = xr[lane + k * 32];
        float4 o;
        o.x = xv.x + (v[k].x - mu) * rstd * g2[c + 0] + b2[c + 0];
        o.y = xv.y + (v[k].y - mu) * rstd * g2[c + 1] + b2[c + 1];
        o.z = xv.z + (v[k].z - mu) * rstd * g2[c + 2] + b2[c + 2];
        o.w = xv.w + (v[k].w - mu) * rstd * g2[c + 3] + b2[c + 3];
        o1[lane + k * 32] = o;
    }
}

// ---------------- launch ----------------
extern "C" void kernel_launch(void* const* d_in, const int* in_sizes, int n_in,
                              void* d_out, int out_size) {
    const float* x        = (const float*)d_in[0];
    const float* qkv_w    = (const float*)d_in[1];
    const float* q_bias   = (const float*)d_in[2];
    const float* v_bias   = (const float*)d_in[3];
    const float* proj_w   = (const float*)d_in[4];
    const float* proj_b   = (const float*)d_in[5];
    const float* lscale   = (const float*)d_in[6];
    const float* cpb_w1   = (const float*)d_in[7];
    const float* cpb_b1   = (const float*)d_in[8];
    const float* cpb_w2   = (const float*)d_in[9];
    const float* rct      = (const float*)d_in[10];
    const float* gamma1   = (const float*)d_in[11];
    const float* beta1    = (const float*)d_in[12];
    const float* gamma2   = (const float*)d_in[13];
    const float* beta2    = (const float*)d_in[14];
    const float* fc1_w    = (const float*)d_in[15];
    const float* fc1_b    = (const float*)d_in[16];
    const float* fc2_w    = (const float*)d_in[17];
    const float* fc2_b    = (const float*)d_in[18];
    const int*   rpi      = (const int*)d_in[19];
    const float* amask    = (const float*)d_in[20];
    float* out = (float*)d_out;

    float *p_qkv, *p_proj, *p_h2;
    __half *p_xw16, *p_attn16, *p_x1h, *p_hid16;
    __half *wt_qkv, *wt_proj, *wt_fc1, *wt_fc2;
    cudaGetSymbolAddress((void**)&p_qkv,    g_qkv);
    cudaGetSymbolAddress((void**)&p_proj,   g_proj);
    cudaGetSymbolAddress((void**)&p_h2,     g_h2);
    cudaGetSymbolAddress((void**)&p_xw16,   g_xw16);
    cudaGetSymbolAddress((void**)&p_attn16, g_attn16);
    cudaGetSymbolAddress((void**)&p_x1h,    g_x1h);
    cudaGetSymbolAddress((void**)&p_hid16,  g_hid16);
    cudaGetSymbolAddress((void**)&wt_qkv,   g_wt_qkv);
    cudaGetSymbolAddress((void**)&wt_proj,  g_wt_proj);
    cudaGetSymbolAddress((void**)&wt_fc1,   g_wt_fc1);
    cudaGetSymbolAddress((void**)&wt_fc2,   g_wt_fc2);

    cudaFuncSetAttribute(hgemm_kernel<MODE_QKV>,
                         cudaFuncAttributeMaxDynamicSharedMemorySize, HG_SMEM);
    cudaFuncSetAttribute(hgemm_kernel<MODE_BIAS>,
                         cudaFuncAttributeMaxDynamicSharedMemorySize, HG_SMEM);
    cudaFuncSetAttribute(hgemm_kernel<MODE_GELU_H>,
                         cudaFuncAttributeMaxDynamicSharedMemorySize, HG_SMEM);

    // 0. weight transposes + fp16 convert; gather x
    transpose_kernel<<<dim3(1536 / 32, 512 / 32), dim3(32, 8)>>>(qkv_w, wt_qkv, 512, 1536);
    transpose_kernel<<<dim3(512 / 32, 512 / 32),  dim3(32, 8)>>>(proj_w, wt_proj, 512, 512);
    transpose_kernel<<<dim3(2048 / 32, 512 / 32), dim3(32, 8)>>>(fc1_w, wt_fc1, 512, 2048);
    transpose_kernel<<<dim3(512 / 32, 2048 / 32), dim3(32, 8)>>>(fc2_w, wt_fc2, 2048, 512);
    gather_x_kernel<<<TOK / 2, 256>>>(x);

    // 1. continuous position bias
    cpb_table_kernel<<<169, 512>>>(rct, cpb_w1, cpb_b1, cpb_w2);
    bias_expand_kernel<<<(16 * 2401 + 255) / 256, 256>>>(rpi);

    // 2. QKV GEMM
    hgemm_kernel<MODE_QKV><<<dim3(1536 / 128, TOK / 128), 256, HG_SMEM>>>(
        p_xw16, wt_qkv, p_qkv, TOK, 1536, 512, q_bias, v_bias);

    // 3. windowed cosine attention
    attn_kernel<<<NWIN * NHEAD, 256>>>(amask, lscale);

    // 4. output projection
    hgemm_kernel<MODE_BIAS><<<dim3(CDIM / 128, TOK / 128), 256, HG_SMEM>>>(
        p_attn16, wt_proj, p_proj, TOK, CDIM, CDIM, proj_b, nullptr);

    // 5. window reverse + un-roll + LN + residual
    post_attn_kernel<<<TOK / 8, 256>>>(x, gamma1, beta1);

    // 6. MLP
    hgemm_kernel<MODE_GELU_H><<<dim3(HID / 128, TOK / 128), 256, HG_SMEM>>>(
        p_x1h, wt_fc1, p_hid16, TOK, HID, 512, fc1_b, nullptr);
    hgemm_kernel<MODE_BIAS><<<dim3(CDIM / 128, TOK / 128), 256, HG_SMEM>>>(
        p_hid16, wt_fc2, p_h2, TOK, CDIM, HID, fc2_b, nullptr);

    // 7. final LN + residual
    final_kernel<<<TOK / 8, 256>>>(gamma2, beta2, out);
}